// round 12
// baseline (speedup 1.0000x reference)
#include <cuda_runtime.h>
#include <cstdint>

#define BI 32
#define HH 512
#define WW 512
#define HW (HH*WW)

__device__ unsigned long long g_strong[BI][HH][8];
__device__ unsigned long long g_weak[BI][HH][8];

// u8 = floor(clip((x+1)*0.5*256, 0, 255)); fma(v,128,128) bit-exact; tanh input >= -1.
__device__ __forceinline__ float pix_u8(float v){
    float t = __fmaf_rn(v, 128.0f, 128.0f);
    t = fminf(t, 255.0f);
    return floorf(t);
}
// gray = round(0.299r+0.587g+0.114b). Magic-add rounding: for 0 <= s < 2^22,
// (s + 12582912.0f) - 12582912.0f == rint(s) bit-exactly (round-half-even).
__device__ __forceinline__ float grayv(float r, float g, float b){
    float s = __fadd_rn(__fadd_rn(__fmul_rn(0.299f, r), __fmul_rn(0.587f, g)),
                        __fmul_rn(0.114f, b));
    float t = __fadd_rn(s, 12582912.0f);
    return __fadd_rn(t, -12582912.0f);
}
// Exact fp32 integer direction binning (gx,gy integers, |.|<=1020; products < 2^24)
__device__ __forceinline__ int binOf(float gx, float gy){
    float ax = fabsf(gx), ay = fabsf(gy);
    float sum = __fadd_rn(ax, ay);
    float a2  = __fmul_rn(2.0f, __fmul_rn(ax, ax));
    if (__fmul_rn(sum, sum) < a2) return 0;
    float dif = __fadd_rn(ay, -ax);
    if (dif > 0.0f && __fmul_rn(dif, dif) > a2) return 2;
    return (__fmul_rn(gx, gy) > 0.0f) ? 1 : 3;
}

#define TW 64
#define TH 32
#define GH 36
#define GW 72            // ig i <-> image col col0-4+i; stencils use ig 2..69
#define MH 34
#define MW 66

#define SOBEL(jj, ii, GX, GY)                                                         \
    {                                                                                 \
        float g00 = gs[jj  ][ii+2], g01 = gs[jj  ][ii+3], g02 = gs[jj  ][ii+4];       \
        float g10 = gs[jj+1][ii+2],                       g12 = gs[jj+1][ii+4];       \
        float g20 = gs[jj+2][ii+2], g21 = gs[jj+2][ii+3], g22 = gs[jj+2][ii+4];       \
        GX = (g02 + 2.0f*g12 + g22) - (g00 + 2.0f*g10 + g20);                         \
        GY = (g20 + 2.0f*g21 + g22) - (g00 + 2.0f*g01 + g02);                         \
    }

__global__ __launch_bounds__(256, 5) void canny_stage1(const float* __restrict__ x){
    __shared__ float gs[GH][GW];   // gray
    __shared__ float ms[MH][MW];   // |gx|+|gy|, zero outside image, halo 1

    int b    = blockIdx.z;
    int col0 = blockIdx.x * TW;
    int row0 = blockIdx.y * TH;
    int tx   = threadIdx.x;    // 0..63
    int ty   = threadIdx.y;    // 0..3
    int tid  = ty*64 + tx;

    const float* xr = x + (size_t)b * 3 * HW;
    const float* xg = xr + HW;
    const float* xb = xg + HW;

    bool leftT  = (col0 == 0);
    bool rightT = (col0 == WW - TW);

    // ---- Phase 1: gray; compact float4 loop, incremental slot addressing ----
    {
        const int NE = GH * 18;               // 648 float4 slots (72 cols/row)
        int j0 = tid / 18, q0 = tid - 18*j0;  // first slot
        int j = j0, q = q0;
        for (int s = tid; s < NE; s += 256){
            int r = min(max(row0 - 2 + j, 0), HH-1);
            int c = min(max(col0 - 4 + 4*q, 0), WW-4);
            int off = r*WW + c;
            float4 rv = *(const float4*)(xr + off);
            float4 gv = *(const float4*)(xg + off);
            float4 bv = *(const float4*)(xb + off);
            bool skip = (leftT && q == 0) || (rightT && q == 17);
            if (!skip){
                float4 o;
                o.x = grayv(pix_u8(rv.x), pix_u8(gv.x), pix_u8(bv.x));
                o.y = grayv(pix_u8(rv.y), pix_u8(gv.y), pix_u8(bv.y));
                o.z = grayv(pix_u8(rv.z), pix_u8(gv.z), pix_u8(bv.z));
                o.w = grayv(pix_u8(rv.w), pix_u8(gv.w), pix_u8(bv.w));
                *(float4*)&gs[j][4*q] = o;
            }
            // advance 256 slots = 14 rows + 4 cols (14*18+4 = 256)
            j += 14; q += 4;
            if (q >= 18){ q -= 18; j += 1; }
        }
        // edge tiles: replicate-clamp gray halo cols
        if ((leftT || rightT) && tid < GH){
            int jj = tid;
            int r = min(max(row0 - 2 + jj, 0), HH-1);
            int c = leftT ? 0 : (WW-1);
            int off = r*WW + c;
            float v = grayv(pix_u8(xr[off]), pix_u8(xg[off]), pix_u8(xb[off]));
            int ig = leftT ? 2 : 68;
            gs[jj][ig] = v; gs[jj][ig+1] = v;
        }
    }
    __syncthreads();

    // ---- Phase 2: sliding-window Sobel; thread owns ms col tx+1, rows jbeg..jbeg+8.
    //      m for own output rows (k2=1..8) kept in registers for phase 3. ----
    unsigned binreg = 0;
    float mreg[8];
    {
        int i   = tx + 1;
        int igL = tx + 3, igC = tx + 4, igR = tx + 5;
        int jbeg = 8*ty;
        float g0L = gs[jbeg  ][igL], g0C = gs[jbeg  ][igC], g0R = gs[jbeg  ][igR];
        float g1L = gs[jbeg+1][igL], g1C = gs[jbeg+1][igC], g1R = gs[jbeg+1][igR];
        #pragma unroll
        for (int k2 = 0; k2 < 9; ++k2){
            int j = jbeg + k2;
            float g2L = gs[j+2][igL], g2C = gs[j+2][igC], g2R = gs[j+2][igR];
            float csL = __fmaf_rn(g1L, 2.0f, g0L) + g2L;
            float csR = __fmaf_rn(g1R, 2.0f, g0R) + g2R;
            float vdL = g2L - g0L, vdC = g2C - g0C, vdR = g2R - g0R;
            float gx  = csR - csL;
            float gy  = __fmaf_rn(vdC, 2.0f, vdL) + vdR;
            float m   = fabsf(gx) + fabsf(gy);
            int r = row0 - 1 + j;
            if (r < 0 || r >= HH) m = 0.0f;     // only j==0@row0==0 / j==33@row0==480
            ms[j][i] = m;
            if (k2 >= 1){                        // own output rows (always in-image)
                mreg[k2-1] = m;
                binreg |= (unsigned)binOf(gx, gy) << (2*(k2-1));
            }
            g0L = g1L; g0C = g1C; g0R = g1R;
            g1L = g2L; g1C = g2C; g1R = g2R;
        }
    }
    // halo row j=33 (ty==3 threads; rows 24..32 done above)
    if (ty == 3){
        int j = 33, i = tx + 1;
        int r = row0 + 32;
        float m = 0.0f;
        if (r < HH){
            float gx, gy;
            SOBEL(j, i, gx, gy)
            m = fabsf(gx) + fabsf(gy);
        }
        ms[j][i] = m;
    }
    // halo cols i=0 and i=65: 68 threads, 1 stencil each
    if (tid < 2*MH){
        int j = tid >> 1;
        int i = (tid & 1) ? (MW-1) : 0;
        int cg = col0 - 1 + ((tid & 1) ? 65 : 0);
        int r  = row0 - 1 + j;
        float m = 0.0f;
        if (cg >= 0 && cg < WW && r >= 0 && r < HH){
            float gx, gy;
            SOBEL(j, i, gx, gy)
            m = fabsf(gx) + fabsf(gy);
        }
        ms[j][i] = m;
    }
    __syncthreads();

    // ---- Phase 3: NMS + thresholds -> ballots (center m from registers) ----
    int lane = tx & 31;
    int wsel = tx >> 5;
    const float* msf = &ms[0][0];
    #pragma unroll
    for (int k = 0; k < 8; k++){
        int tyr  = 8*ty + k;                   // tile row of own pixel
        int cidx = (tyr+1)*MW + (tx+1);
        float m  = mreg[k];
        int bin  = (binreg >> (2*k)) & 3;
        // antisymmetric offsets: bin0 (0,±1); bin1 (±1,±1); bin2 (±1,0); bin3 (∓1,±1)
        int o1 = (bin==0) ? 1 : (bin==1) ? (MW+1) : (bin==2) ? MW : (1-MW);
        float q1 = msf[cidx + o1];
        float q2 = msf[cidx - o1];
        bool ok = (m >= q1) && (m >= q2);

        unsigned sbits = __ballot_sync(0xffffffffu, ok && (m > 85.0f));
        unsigned wbits = __ballot_sync(0xffffffffu, ok && (m > 40.0f));
        if (lane == 0){
            int grow = row0 + tyr;
            int word = (col0 >> 5) + wsel;
            ((unsigned*)g_strong)[((size_t)b*HH + grow)*16 + word] = sbits;
            ((unsigned*)g_weak  )[((size_t)b*HH + grow)*16 + word] = wbits;
        }
    }
}

// Hysteresis, row-split: 4 CTAs per image, 128 own rows + 100-row halos.
// Dilation moves <=1 row/iter, iters <=100 -> own rows bit-exact vs full image.
#define OWN 128
#define HALO 100
#define SPAN 352
#define NW 11
__global__ __launch_bounds__(SPAN) void canny_hyst(float* __restrict__ out){
    __shared__ unsigned long long hb[NW][2][8];
    __shared__ unsigned long long sb2[OWN][8];

    int b    = blockIdx.y;
    int base = blockIdx.x * OWN;
    int lr   = threadIdx.x;          // 0..351
    int gr   = base - HALO + lr;     // global row
    int lane = lr & 31;
    int warp = lr >> 5;
    bool inim = (gr >= 0 && gr < HH);

    cudaGridDependencySynchronize();

    unsigned long long w[8], s[8];
    #pragma unroll
    for (int i = 0; i < 8; i++){
        w[i] = inim ? g_weak[b][gr][i]   : 0ull;
        s[i] = inim ? g_strong[b][gr][i] : 0ull;
    }

    for (int it = 0; it < 100; ++it){
        unsigned long long h[8];
        #pragma unroll
        for (int i = 0; i < 8; i++) h[i] = s[i] | (s[i] << 1) | (s[i] >> 1);
        #pragma unroll
        for (int i = 0; i < 7; i++){ h[i+1] |= s[i] >> 63; h[i] |= s[i+1] << 63; }

        unsigned long long up[8], dn[8];
        #pragma unroll
        for (int i = 0; i < 8; i++){
            up[i] = __shfl_up_sync  (0xffffffffu, h[i], 1);
            dn[i] = __shfl_down_sync(0xffffffffu, h[i], 1);
        }
        if (lane == 0){
            #pragma unroll
            for (int i = 0; i < 8; i++) hb[warp][0][i] = h[i];
        }
        if (lane == 31){
            #pragma unroll
            for (int i = 0; i < 8; i++) hb[warp][1][i] = h[i];
        }
        __syncthreads();
        if (lane == 0){
            if (warp > 0){
                #pragma unroll
                for (int i = 0; i < 8; i++) up[i] = hb[warp-1][1][i];
            } else {
                #pragma unroll
                for (int i = 0; i < 8; i++) up[i] = 0ull;
            }
        }
        if (lane == 31){
            if (warp < NW-1){
                #pragma unroll
                for (int i = 0; i < 8; i++) dn[i] = hb[warp+1][0][i];
            } else {
                #pragma unroll
                for (int i = 0; i < 8; i++) dn[i] = 0ull;
            }
        }

        unsigned long long ch = 0ull;
        #pragma unroll
        for (int i = 0; i < 8; i++){
            unsigned long long ns = (h[i] | up[i] | dn[i]) & w[i];
            ch |= ns ^ s[i];
            s[i] = ns;
        }
        if (!__syncthreads_or(ch != 0ull)) break;
    }

    int orow = lr - HALO;
    if (orow >= 0 && orow < OWN){
        #pragma unroll
        for (int i = 0; i < 8; i++) sb2[orow][i] = s[i];
    }
    __syncthreads();

    float* o = out + (size_t)b * HW + (size_t)base * WW;
    for (int j = threadIdx.x; j < OWN*WW/4; j += SPAN){
        int pix = j << 2;
        unsigned long long wv = sb2[pix >> 9][(pix >> 6) & 7];
        int sh = pix & 63;
        float4 v;
        v.x = ((wv >> (sh    )) & 1ull) ? 255.0f : 0.0f;
        v.y = ((wv >> (sh + 1)) & 1ull) ? 255.0f : 0.0f;
        v.z = ((wv >> (sh + 2)) & 1ull) ? 255.0f : 0.0f;
        v.w = ((wv >> (sh + 3)) & 1ull) ? 255.0f : 0.0f;
        ((float4*)o)[j] = v;
    }
}

extern "C" void kernel_launch(void* const* d_in, const int* in_sizes, int n_in,
                              void* d_out, int out_size){
    const float* x = (const float*)d_in[0];
    dim3 g1(WW/TW, HH/TH, BI), b1(64, 4, 1);
    canny_stage1<<<g1, b1>>>(x);

    cudaLaunchConfig_t cfg = {};
    cfg.gridDim  = dim3(HH/OWN, BI, 1);
    cfg.blockDim = dim3(SPAN, 1, 1);
    cfg.dynamicSmemBytes = 0;
    cfg.stream = 0;
    cudaLaunchAttribute at[1];
    at[0].id = cudaLaunchAttributeProgrammaticStreamSerialization;
    at[0].val.programmaticStreamSerializationAllowed = 1;
    cfg.attrs = at;
    cfg.numAttrs = 1;
    cudaLaunchKernelEx(&cfg, canny_hyst, (float*)d_out);
}

// round 13
// speedup vs baseline: 1.0741x; 1.0741x over previous
#include <cuda_runtime.h>
#include <cstdint>

#define BI 32
#define HH 512
#define WW 512
#define HW (HH*WW)

__device__ unsigned long long g_strong[BI][HH][8];
__device__ unsigned long long g_weak[BI][HH][8];

// u8 = floor(clip((x+1)*0.5*256, 0, 255)); fma(v,128,128) bit-exact; tanh input >= -1.
__device__ __forceinline__ float pix_u8(float v){
    float t = __fmaf_rn(v, 128.0f, 128.0f);
    t = fminf(t, 255.0f);
    return floorf(t);
}
// gray = round(0.299r+0.587g+0.114b). Magic-add rounding: for 0 <= s < 2^22,
// (s + 12582912.0f) - 12582912.0f == rint(s) bit-exactly (round-half-even).
__device__ __forceinline__ float grayv(float r, float g, float b){
    float s = __fadd_rn(__fadd_rn(__fmul_rn(0.299f, r), __fmul_rn(0.587f, g)),
                        __fmul_rn(0.114f, b));
    float t = __fadd_rn(s, 12582912.0f);
    return __fadd_rn(t, -12582912.0f);
}
// Exact fp32 integer direction binning (gx,gy integers, |.|<=1020; products < 2^24)
__device__ __forceinline__ int binOf(float gx, float gy){
    float ax = fabsf(gx), ay = fabsf(gy);
    float sum = __fadd_rn(ax, ay);
    float a2  = __fmul_rn(2.0f, __fmul_rn(ax, ax));
    if (__fmul_rn(sum, sum) < a2) return 0;
    float dif = __fadd_rn(ay, -ax);
    if (dif > 0.0f && __fmul_rn(dif, dif) > a2) return 2;
    return (__fmul_rn(gx, gy) > 0.0f) ? 1 : 3;
}

#define TW 64
#define TH 32
#define GH 36
#define GW 72            // ig i <-> image col col0-4+i; stencils use ig 2..69
#define MH 34
#define MW 66

#define SOBEL(jj, ii, GX, GY)                                                         \
    {                                                                                 \
        float g00 = gs[jj  ][ii+2], g01 = gs[jj  ][ii+3], g02 = gs[jj  ][ii+4];       \
        float g10 = gs[jj+1][ii+2],                       g12 = gs[jj+1][ii+4];       \
        float g20 = gs[jj+2][ii+2], g21 = gs[jj+2][ii+3], g22 = gs[jj+2][ii+4];       \
        GX = (g02 + 2.0f*g12 + g22) - (g00 + 2.0f*g10 + g20);                         \
        GY = (g20 + 2.0f*g21 + g22) - (g00 + 2.0f*g01 + g02);                         \
    }

__global__ __launch_bounds__(256, 5) void canny_stage1(const float* __restrict__ x){
    __shared__ float gs[GH][GW];   // gray
    __shared__ float ms[MH][MW];   // |gx|+|gy|, zero outside image, halo 1

    int b    = blockIdx.z;
    int col0 = blockIdx.x * TW;
    int row0 = blockIdx.y * TH;
    int tx   = threadIdx.x;    // 0..63
    int ty   = threadIdx.y;    // 0..3
    int tid  = ty*64 + tx;

    const float* xr = x + (size_t)b * 3 * HW;
    const float* xg = xr + HW;
    const float* xb = xg + HW;

    bool leftT  = (col0 == 0);
    bool rightT = (col0 == WW - TW);

    // ---- Phase 1: gray; compact float4 loop with clamped addresses ----
    {
        const int NE = GH * 18;               // 648 float4 slots (72 cols/row)
        for (int s = tid; s < NE; s += 256){
            int j = s / 18, q = s - 18*j;
            int r = min(max(row0 - 2 + j, 0), HH-1);
            int c = min(max(col0 - 4 + 4*q, 0), WW-4);
            int off = r*WW + c;
            float4 rv = *(const float4*)(xr + off);
            float4 gv = *(const float4*)(xg + off);
            float4 bv = *(const float4*)(xb + off);
            bool skip = (leftT && q == 0) || (rightT && q == 17);
            if (!skip){
                float4 o;
                o.x = grayv(pix_u8(rv.x), pix_u8(gv.x), pix_u8(bv.x));
                o.y = grayv(pix_u8(rv.y), pix_u8(gv.y), pix_u8(bv.y));
                o.z = grayv(pix_u8(rv.z), pix_u8(gv.z), pix_u8(bv.z));
                o.w = grayv(pix_u8(rv.w), pix_u8(gv.w), pix_u8(bv.w));
                *(float4*)&gs[j][4*q] = o;
            }
        }
        // edge tiles: replicate-clamp gray halo cols
        if ((leftT || rightT) && tid < GH){
            int j = tid;
            int r = min(max(row0 - 2 + j, 0), HH-1);
            int c = leftT ? 0 : (WW-1);
            int off = r*WW + c;
            float v = grayv(pix_u8(xr[off]), pix_u8(xg[off]), pix_u8(xb[off]));
            int ig = leftT ? 2 : 68;
            gs[j][ig] = v; gs[j][ig+1] = v;
        }
    }
    __syncthreads();

    // ---- Phase 2: sliding-window Sobel; thread owns ms col tx+1, 9 consecutive
    //      rows jbeg..jbeg+8 (jbeg = 8*ty; rows 8,16,24 written twice w/ same value) ----
    unsigned binreg = 0;
    {
        int i   = tx + 1;
        int igL = tx + 3, igC = tx + 4, igR = tx + 5;
        int jbeg = 8*ty;
        float g0L = gs[jbeg  ][igL], g0C = gs[jbeg  ][igC], g0R = gs[jbeg  ][igR];
        float g1L = gs[jbeg+1][igL], g1C = gs[jbeg+1][igC], g1R = gs[jbeg+1][igR];
        #pragma unroll
        for (int k2 = 0; k2 < 9; ++k2){
            int j = jbeg + k2;
            float g2L = gs[j+2][igL], g2C = gs[j+2][igC], g2R = gs[j+2][igR];
            float csL = __fmaf_rn(g1L, 2.0f, g0L) + g2L;
            float csR = __fmaf_rn(g1R, 2.0f, g0R) + g2R;
            float vdL = g2L - g0L, vdC = g2C - g0C, vdR = g2R - g0R;
            float gx  = csR - csL;
            float gy  = __fmaf_rn(vdC, 2.0f, vdL) + vdR;
            float m   = fabsf(gx) + fabsf(gy);
            int r = row0 - 1 + j;
            if (r < 0 || r >= HH) m = 0.0f;     // only j==0@row0==0 / j==33@row0==480
            ms[j][i] = m;
            if (k2 >= 1){                        // own output rows (always in-image)
                binreg |= (unsigned)binOf(gx, gy) << (2*(k2-1));
            }
            g0L = g1L; g0C = g1C; g0R = g1R;
            g1L = g2L; g1C = g2C; g1R = g2R;
        }
    }
    // halo row j=33 (ty==3 threads; rows 24..32 done above)
    if (ty == 3){
        int j = 33, i = tx + 1;
        int r = row0 + 32;
        float m = 0.0f;
        if (r < HH){
            float gx, gy;
            SOBEL(j, i, gx, gy)
            m = fabsf(gx) + fabsf(gy);
        }
        ms[j][i] = m;
    }
    // halo cols i=0 and i=65: 68 threads, 1 stencil each
    if (tid < 2*MH){
        int j = tid >> 1;
        int i = (tid & 1) ? (MW-1) : 0;
        int cg = col0 - 1 + ((tid & 1) ? 65 : 0);
        int r  = row0 - 1 + j;
        float m = 0.0f;
        if (cg >= 0 && cg < WW && r >= 0 && r < HH){
            float gx, gy;
            SOBEL(j, i, gx, gy)
            m = fabsf(gx) + fabsf(gy);
        }
        ms[j][i] = m;
    }
    __syncthreads();

    // ---- Phase 3: NMS + thresholds -> ballots (rows 8*ty+k per warp) ----
    int lane = tx & 31;
    int wsel = tx >> 5;
    const float* msf = &ms[0][0];
    #pragma unroll
    for (int k = 0; k < 8; k++){
        int tyr  = 8*ty + k;                   // tile row of own pixel
        int cidx = (tyr+1)*MW + (tx+1);
        float m  = msf[cidx];
        int bin  = (binreg >> (2*k)) & 3;
        // antisymmetric offsets: bin0 (0,±1); bin1 (±1,±1); bin2 (±1,0); bin3 (∓1,±1)
        int o1 = (bin==0) ? 1 : (bin==1) ? (MW+1) : (bin==2) ? MW : (1-MW);
        float q1 = msf[cidx + o1];
        float q2 = msf[cidx - o1];
        bool ok = (m >= q1) && (m >= q2);

        unsigned sbits = __ballot_sync(0xffffffffu, ok && (m > 85.0f));
        unsigned wbits = __ballot_sync(0xffffffffu, ok && (m > 40.0f));
        if (lane == 0){
            int grow = row0 + tyr;
            int word = (col0 >> 5) + wsel;
            ((unsigned*)g_strong)[((size_t)b*HH + grow)*16 + word] = sbits;
            ((unsigned*)g_weak  )[((size_t)b*HH + grow)*16 + word] = wbits;
        }
    }
}

// Hysteresis, row-split: 4 CTAs per image, 128 own rows + 100-row halos.
// Dilation moves <=1 row/iter, iters <=100 -> own rows bit-exact vs full image.
#define OWN 128
#define HALO 100
#define SPAN 352
#define NW 11
__global__ __launch_bounds__(SPAN) void canny_hyst(float* __restrict__ out){
    __shared__ unsigned long long hb[NW][2][8];
    __shared__ unsigned long long sb2[OWN][8];

    int b    = blockIdx.y;
    int base = blockIdx.x * OWN;
    int lr   = threadIdx.x;          // 0..351
    int gr   = base - HALO + lr;     // global row
    int lane = lr & 31;
    int warp = lr >> 5;
    bool inim = (gr >= 0 && gr < HH);

    cudaGridDependencySynchronize();

    unsigned long long w[8], s[8];
    #pragma unroll
    for (int i = 0; i < 8; i++){
        w[i] = inim ? g_weak[b][gr][i]   : 0ull;
        s[i] = inim ? g_strong[b][gr][i] : 0ull;
    }

    for (int it = 0; it < 100; ++it){
        unsigned long long h[8];
        #pragma unroll
        for (int i = 0; i < 8; i++) h[i] = s[i] | (s[i] << 1) | (s[i] >> 1);
        #pragma unroll
        for (int i = 0; i < 7; i++){ h[i+1] |= s[i] >> 63; h[i] |= s[i+1] << 63; }

        unsigned long long up[8], dn[8];
        #pragma unroll
        for (int i = 0; i < 8; i++){
            up[i] = __shfl_up_sync  (0xffffffffu, h[i], 1);
            dn[i] = __shfl_down_sync(0xffffffffu, h[i], 1);
        }
        if (lane == 0){
            #pragma unroll
            for (int i = 0; i < 8; i++) hb[warp][0][i] = h[i];
        }
        if (lane == 31){
            #pragma unroll
            for (int i = 0; i < 8; i++) hb[warp][1][i] = h[i];
        }
        __syncthreads();
        if (lane == 0){
            if (warp > 0){
                #pragma unroll
                for (int i = 0; i < 8; i++) up[i] = hb[warp-1][1][i];
            } else {
                #pragma unroll
                for (int i = 0; i < 8; i++) up[i] = 0ull;
            }
        }
        if (lane == 31){
            if (warp < NW-1){
                #pragma unroll
                for (int i = 0; i < 8; i++) dn[i] = hb[warp+1][0][i];
            } else {
                #pragma unroll
                for (int i = 0; i < 8; i++) dn[i] = 0ull;
            }
        }

        unsigned long long ch = 0ull;
        #pragma unroll
        for (int i = 0; i < 8; i++){
            unsigned long long ns = (h[i] | up[i] | dn[i]) & w[i];
            ch |= ns ^ s[i];
            s[i] = ns;
        }
        if (!__syncthreads_or(ch != 0ull)) break;
    }

    int orow = lr - HALO;
    if (orow >= 0 && orow < OWN){
        #pragma unroll
        for (int i = 0; i < 8; i++) sb2[orow][i] = s[i];
    }
    __syncthreads();

    float* o = out + (size_t)b * HW + (size_t)base * WW;
    for (int j = threadIdx.x; j < OWN*WW/4; j += SPAN){
        int pix = j << 2;
        unsigned long long wv = sb2[pix >> 9][(pix >> 6) & 7];
        int sh = pix & 63;
        float4 v;
        v.x = ((wv >> (sh    )) & 1ull) ? 255.0f : 0.0f;
        v.y = ((wv >> (sh + 1)) & 1ull) ? 255.0f : 0.0f;
        v.z = ((wv >> (sh + 2)) & 1ull) ? 255.0f : 0.0f;
        v.w = ((wv >> (sh + 3)) & 1ull) ? 255.0f : 0.0f;
        ((float4*)o)[j] = v;
    }
}

extern "C" void kernel_launch(void* const* d_in, const int* in_sizes, int n_in,
                              void* d_out, int out_size){
    const float* x = (const float*)d_in[0];
    dim3 g1(WW/TW, HH/TH, BI), b1(64, 4, 1);
    canny_stage1<<<g1, b1>>>(x);

    cudaLaunchConfig_t cfg = {};
    cfg.gridDim  = dim3(HH/OWN, BI, 1);
    cfg.blockDim = dim3(SPAN, 1, 1);
    cfg.dynamicSmemBytes = 0;
    cfg.stream = 0;
    cudaLaunchAttribute at[1];
    at[0].id = cudaLaunchAttributeProgrammaticStreamSerialization;
    at[0].val.programmaticStreamSerializationAllowed = 1;
    cfg.attrs = at;
    cfg.numAttrs = 1;
    cudaLaunchKernelEx(&cfg, canny_hyst, (float*)d_out);
}